// round 1
// baseline (speedup 1.0000x reference)
#include <cuda_runtime.h>
#include <math.h>

#define Bn 1024
#define Sn 512
#define Vn 50000
#define En 300
#define Hn 800
#define Tn 50

// ---------------- scratch (device globals; no allocation) ----------------
__device__ float g_x[Bn * En];          // 1.2 MB
__device__ float g_h[Bn * Hn];          // 3.3 MB
__device__ float g_mu[Bn * Tn];
__device__ float g_lv[Bn * Tn];
__device__ float g_logits[Tn * Vn];     // 10 MB
__device__ float g_betaT[(size_t)Vn * 64]; // 12.8 MB, [v][t] padded to 64
__device__ float g_rmax[Tn];
__device__ float g_rinv[Tn];
__device__ float g_recon[Bn];
__device__ float g_kl[Bn];

// ---------------- kernel 1: x[b,:] = (1/cnt) * sum_valid rho[id,:] ----------------
__global__ void k_gather(const int* __restrict__ ids, const float* __restrict__ rho)
{
    __shared__ int sid[Sn];
    __shared__ float s_inv;
    int b = blockIdx.x, tid = threadIdx.x;
    for (int i = tid; i < Sn; i += blockDim.x) {
        int v = ids[b * Sn + i];
        sid[i] = (v == 1 || v == 2) ? -1 : v;
    }
    __syncthreads();
    if (tid < 32) {
        int c = 0;
        for (int i = tid; i < Sn; i += 32) c += (sid[i] >= 0);
#pragma unroll
        for (int o = 16; o; o >>= 1) c += __shfl_down_sync(0xffffffffu, c, o);
        if (tid == 0) s_inv = 1.0f / (float)c;
    }
    __syncthreads();
    if (tid < En) {
        float a0 = 0.f, a1 = 0.f, a2 = 0.f, a3 = 0.f;
        float a4 = 0.f, a5 = 0.f, a6 = 0.f, a7 = 0.f;
        for (int s = 0; s < Sn; s += 8) {
            int v0 = sid[s + 0], v1 = sid[s + 1], v2 = sid[s + 2], v3 = sid[s + 3];
            int v4 = sid[s + 4], v5 = sid[s + 5], v6 = sid[s + 6], v7 = sid[s + 7];
            if (v0 >= 0) a0 += __ldg(&rho[v0 * En + tid]);
            if (v1 >= 0) a1 += __ldg(&rho[v1 * En + tid]);
            if (v2 >= 0) a2 += __ldg(&rho[v2 * En + tid]);
            if (v3 >= 0) a3 += __ldg(&rho[v3 * En + tid]);
            if (v4 >= 0) a4 += __ldg(&rho[v4 * En + tid]);
            if (v5 >= 0) a5 += __ldg(&rho[v5 * En + tid]);
            if (v6 >= 0) a6 += __ldg(&rho[v6 * En + tid]);
            if (v7 >= 0) a7 += __ldg(&rho[v7 * En + tid]);
        }
        float acc = ((a0 + a1) + (a2 + a3)) + ((a4 + a5) + (a6 + a7));
        g_x[b * En + tid] = acc * s_inv;
    }
}

// ---------------- generic tiled fp32 GEMM, C = A @ (B or B^T) + bias, opt relu -------
// A: [M,K] row-major. TRANSB==0: B [K,N]; TRANSB==1: B [N,K].
// Tile: 64(m) x 64(n) x 20(k). 256 threads, each computes 4x4. Requires K % 20 == 0.
template <int TRANSB, int RELU>
__global__ void k_gemm(const float* __restrict__ A, const float* __restrict__ B,
                       const float* __restrict__ bias, float* __restrict__ C,
                       int M, int N, int K)
{
    __shared__ float As[20][65];  // [k][m], padded (transposed write)
    __shared__ float Bs[20][68];  // [k][n], padded to keep 16B row alignment
    int tid = threadIdx.x;
    int m0 = blockIdx.y * 64, n0 = blockIdx.x * 64;
    int my = (tid >> 4) * 4, nx = (tid & 15) * 4;
    float acc[4][4] = {};

    for (int k0 = 0; k0 < K; k0 += 20) {
#pragma unroll
        for (int p = 0; p < 5; p++) {
            int idx = tid + p * 256;  // 1280 elements total per tile
            {   // A tile: (i=m, j=k), coalesced over j
                int i = idx / 20, j = idx % 20;
                int row = m0 + i;
                As[j][i] = (row < M) ? A[(size_t)row * K + k0 + j] : 0.f;
            }
            if (TRANSB) {  // B [N,K]: (i=n, j=k), coalesced over j
                int i = idx / 20, j = idx % 20;
                int col = n0 + i;
                Bs[j][i] = (col < N) ? B[(size_t)col * K + k0 + j] : 0.f;
            } else {       // B [K,N]: (j=k, i=n), coalesced over i
                int j = idx / 64, i = idx % 64;
                int col = n0 + i;
                Bs[j][i] = (col < N) ? B[(size_t)(k0 + j) * N + col] : 0.f;
            }
        }
        __syncthreads();
#pragma unroll
        for (int k = 0; k < 20; k++) {
            float a0 = As[k][my + 0], a1 = As[k][my + 1];
            float a2 = As[k][my + 2], a3 = As[k][my + 3];
            float4 bv = *reinterpret_cast<const float4*>(&Bs[k][nx]);
            acc[0][0] += a0 * bv.x; acc[0][1] += a0 * bv.y; acc[0][2] += a0 * bv.z; acc[0][3] += a0 * bv.w;
            acc[1][0] += a1 * bv.x; acc[1][1] += a1 * bv.y; acc[1][2] += a1 * bv.z; acc[1][3] += a1 * bv.w;
            acc[2][0] += a2 * bv.x; acc[2][1] += a2 * bv.y; acc[2][2] += a2 * bv.z; acc[2][3] += a2 * bv.w;
            acc[3][0] += a3 * bv.x; acc[3][1] += a3 * bv.y; acc[3][2] += a3 * bv.z; acc[3][3] += a3 * bv.w;
        }
        __syncthreads();
    }

#pragma unroll
    for (int i = 0; i < 4; i++) {
        int row = m0 + my + i;
        if (row >= M) continue;
#pragma unroll
        for (int j = 0; j < 4; j++) {
            int col = n0 + nx + j;
            if (col >= N) continue;
            float v = acc[i][j];
            if (bias) v += bias[col];
            if (RELU) v = fmaxf(v, 0.f);
            C[(size_t)row * N + col] = v;
        }
    }
}

// ---------------- beta softmax: pass 1 (row max + 1/sum) ----------------
__global__ void k_beta_stats()
{
    int t = blockIdx.x;      // 50 rows
    int tid = threadIdx.x;   // 256
    __shared__ float red[256];
    const float* row = g_logits + (size_t)t * Vn;
    float m = -1e30f;
    for (int v = tid; v < Vn; v += 256) m = fmaxf(m, row[v]);
    red[tid] = m; __syncthreads();
    for (int o = 128; o; o >>= 1) { if (tid < o) red[tid] = fmaxf(red[tid], red[tid + o]); __syncthreads(); }
    float M = red[0]; __syncthreads();
    float s = 0.f;
    for (int v = tid; v < Vn; v += 256) s += expf(row[v] - M);
    red[tid] = s; __syncthreads();
    for (int o = 128; o; o >>= 1) { if (tid < o) red[tid] += red[tid + o]; __syncthreads(); }
    if (tid == 0) { g_rmax[t] = M; g_rinv[t] = 1.0f / red[0]; }
}

// ---------------- beta softmax: pass 2, write transposed betaT[v*64+t] ----------------
__global__ void k_beta_write()
{
    __shared__ float tile[64][129];
    int v0 = blockIdx.x * 128;
    int tid = threadIdx.x;  // 256
    for (int idx = tid; idx < 64 * 128; idx += 256) {
        int t = idx >> 7, vi = idx & 127;
        float val = 0.f;
        int v = v0 + vi;
        if (t < Tn && v < Vn)
            val = expf(g_logits[(size_t)t * Vn + v] - g_rmax[t]) * g_rinv[t];
        tile[t][vi] = val;
    }
    __syncthreads();
    for (int idx = tid; idx < 64 * 128; idx += 256) {
        int vi = idx >> 6, t = idx & 63;
        int v = v0 + vi;
        if (v < Vn) g_betaT[(size_t)v * 64 + t] = tile[t][vi];
    }
}

// ---------------- kl + theta softmax; theta -> d_out ----------------
__global__ void k_theta_kl(float* __restrict__ out)
{
    int b = blockIdx.x, t = threadIdx.x;  // 64 threads
    __shared__ float red[64];
    bool ok = (t < Tn);
    float mu = 0.f, lv = 0.f;
    if (ok) { mu = g_mu[b * Tn + t]; lv = g_lv[b * Tn + t]; }
    float kle = ok ? (1.f + lv - mu * mu - expf(lv)) : 0.f;
    red[t] = kle; __syncthreads();
    for (int o = 32; o; o >>= 1) { if (t < o) red[t] += red[t + o]; __syncthreads(); }
    if (t == 0) g_kl[b] = -0.5f * red[0];
    __syncthreads();
    red[t] = ok ? mu : -1e30f; __syncthreads();
    for (int o = 32; o; o >>= 1) { if (t < o) red[t] = fmaxf(red[t], red[t + o]); __syncthreads(); }
    float mx = red[0]; __syncthreads();
    float e = ok ? expf(mu - mx) : 0.f;
    red[t] = e; __syncthreads();
    for (int o = 32; o; o >>= 1) { if (t < o) red[t] += red[t + o]; __syncthreads(); }
    float inv = 1.0f / red[0];
    if (ok) out[b * Tn + t] = e * inv;
}

// ---------------- recon[b] = -sum_valid log(theta_b . betaT[id] + 1e-5) ----------------
__global__ void k_recon(const int* __restrict__ ids, const float* __restrict__ theta)
{
    int b = blockIdx.x;
    int tid = threadIdx.x;  // 256 = 8 warps
    __shared__ float th[64];
    __shared__ float wsum[8];
    if (tid < 64) th[tid] = (tid < Tn) ? theta[b * Tn + tid] : 0.f;
    __syncthreads();
    int warp = tid >> 5, lane = tid & 31;
    float t0 = th[lane], t1 = th[lane + 32];
    float acc = 0.f;
    for (int s = warp; s < Sn; s += 8) {
        int v = ids[b * Sn + s];
        if (v != 1 && v != 2) {
            const float* p = g_betaT + (size_t)v * 64;
            float d = t0 * p[lane] + t1 * p[lane + 32];
#pragma unroll
            for (int o = 16; o; o >>= 1) d += __shfl_down_sync(0xffffffffu, d, o);
            d = __shfl_sync(0xffffffffu, d, 0);
            if (lane == 0) acc += logf(d + 1e-5f);
        }
    }
    if (lane == 0) wsum[warp] = acc;
    __syncthreads();
    if (tid == 0) {
        float s = 0.f;
        for (int i = 0; i < 8; i++) s += wsum[i];
        g_recon[b] = -s;
    }
}

// ---------------- final loss = mean(recon) + mean(kl) ----------------
__global__ void k_loss(float* __restrict__ out, int loss_idx)
{
    __shared__ float r1[1024];
    __shared__ float r2[1024];
    int t = threadIdx.x;  // 1024
    r1[t] = g_recon[t]; r2[t] = g_kl[t];
    __syncthreads();
    for (int o = 512; o; o >>= 1) {
        if (t < o) { r1[t] += r1[t + o]; r2[t] += r2[t + o]; }
        __syncthreads();
    }
    if (t == 0) out[loss_idx] = (r1[0] + r2[0]) * (1.0f / (float)Bn);
}

// ---------------- launch ----------------
extern "C" void kernel_launch(void* const* d_in, const int* in_sizes, int n_in,
                              void* d_out, int out_size)
{
    const int*   ids   = (const int*)d_in[0];
    const float* rho   = (const float*)d_in[1];
    const float* alpha = (const float*)d_in[2];
    const float* W1    = (const float*)d_in[3];
    const float* b1    = (const float*)d_in[4];
    const float* Wmu   = (const float*)d_in[5];
    const float* bmu   = (const float*)d_in[6];
    const float* Wlv   = (const float*)d_in[7];
    const float* blv   = (const float*)d_in[8];
    float* out = (float*)d_out;

    void *p_x, *p_h, *p_mu, *p_lv, *p_logits;
    cudaGetSymbolAddress(&p_x, g_x);
    cudaGetSymbolAddress(&p_h, g_h);
    cudaGetSymbolAddress(&p_mu, g_mu);
    cudaGetSymbolAddress(&p_lv, g_lv);
    cudaGetSymbolAddress(&p_logits, g_logits);
    float* fx = (float*)p_x;
    float* fh = (float*)p_h;
    float* fmu = (float*)p_mu;
    float* flv = (float*)p_lv;
    float* flog = (float*)p_logits;

    // 1) x = gather(rho, ids) / count
    k_gather<<<Bn, 320>>>(ids, rho);

    // 2) h = relu(x @ W1 + b1)   [1024,300]x[300,800]
    {
        dim3 g((Hn + 63) / 64, (Bn + 63) / 64);
        k_gemm<0, 1><<<g, 256>>>(fx, W1, b1, fh, Bn, Hn, En);
    }
    // 3) mu = h @ Wmu + bmu ; lv = h @ Wlv + blv   [1024,800]x[800,50]
    {
        dim3 g((Tn + 63) / 64, (Bn + 63) / 64);
        k_gemm<0, 0><<<g, 256>>>(fh, Wmu, bmu, fmu, Bn, Tn, Hn);
        k_gemm<0, 0><<<g, 256>>>(fh, Wlv, blv, flv, Bn, Tn, Hn);
    }
    // 4) logits = alpha @ rho^T   [50,300]x[50000,300]^T
    {
        dim3 g((Vn + 63) / 64, (Tn + 63) / 64);
        k_gemm<1, 0><<<g, 256>>>(alpha, rho, (const float*)nullptr, flog, Tn, Vn, En);
    }
    // 5) beta = softmax(logits) over V, stored transposed/padded as betaT[v*64+t]
    k_beta_stats<<<Tn, 256>>>();
    k_beta_write<<<(Vn + 127) / 128, 256>>>();

    // 6) kl + theta softmax (theta written straight into d_out)
    k_theta_kl<<<Bn, 64>>>(out);

    // 7) recon loss per row (sparse token gather on betaT)
    k_recon<<<Bn, 256>>>(ids, out);

    // 8) loss scalar
    k_loss<<<1, 1024>>>(out, out_size - 1);
}